// round 5
// baseline (speedup 1.0000x reference)
#include <cuda_runtime.h>
#include <cuda_bf16.h>
#include <cstdint>
#include <cmath>

#define HIDN 1024
#define EMBD 1024
#define BATCH 256
#define SEQL 128
#define NCLS 32000
#define NG   4096   /* 4*HIDN, gate-interleaved: n = 4*j + g */

#define BM 128
#define BN 64
#define BK 16
#define AS 20
#define BSS 20
#define GS 68
#define VSTR 516

#define NCTA 128
#define PTHREADS 256

// ---------------- device scratch (no allocations allowed) ----------------
static __device__ unsigned g_Ub[NG * (HIDN / 2)];            // 8 MB interleaved U, bf16x2
static __device__ unsigned g_Vb[NG * (HIDN / 2)];            // 8 MB interleaved V, bf16x2
static __device__ unsigned g_Eb[(size_t)NCLS * (EMBD / 2)];  // 64 MB emb, bf16x2
static __device__ float    g_ball[NG];
static __device__ float    g_h[2][BATCH * HIDN];             // fp32 h (final proj reads [0])
static __device__ unsigned g_hb[2][BATCH * (HIDN / 2)];      // bf16x2 h ping-pong
static __device__ float    g_c[BATCH * HIDN];
static __device__ unsigned g_bar;                            // grid barrier

// ---------------- helpers ----------------
__device__ __forceinline__ float f2tf32(float x) {
    uint32_t r;
    asm("cvt.rna.tf32.f32 %0, %1;" : "=r"(r) : "f"(x));
    return __uint_as_float(r);
}
__device__ __forceinline__ unsigned pack_bf2(float a, float b) {
    __nv_bfloat162 v = __floats2bfloat162_rn(a, b);
    return *reinterpret_cast<unsigned*>(&v);
}
__device__ __forceinline__ float fsig(float x) {
    return __fdividef(1.f, 1.f + __expf(-x));
}
__device__ __forceinline__ void mma_bf16(float* acc, const unsigned* a, const unsigned* b) {
    asm volatile(
        "mma.sync.aligned.m16n8k16.row.col.f32.bf16.bf16.f32 "
        "{%0,%1,%2,%3}, {%4,%5,%6,%7}, {%8,%9}, {%0,%1,%2,%3};"
        : "+f"(acc[0]), "+f"(acc[1]), "+f"(acc[2]), "+f"(acc[3])
        : "r"(a[0]), "r"(a[1]), "r"(a[2]), "r"(a[3]), "r"(b[0]), "r"(b[1]));
}

// ---------------- pack: interleave U/V (bf16), biases, init state ----------------
__global__ void pack_kernel(const float* __restrict__ Ui, const float* __restrict__ Vi, const float* __restrict__ bi,
                            const float* __restrict__ Uf, const float* __restrict__ Vf, const float* __restrict__ bf,
                            const float* __restrict__ Uc, const float* __restrict__ Vc, const float* __restrict__ bc,
                            const float* __restrict__ Uo, const float* __restrict__ Vo, const float* __restrict__ bo,
                            const float* __restrict__ h0, const float* __restrict__ c0)
{
    int idx = blockIdx.x * blockDim.x + threadIdx.x;   // over NG * 512 half2 units
    if (idx >= NG * (HIDN / 2)) return;
    if (idx == 0) g_bar = 0u;
    int n = idx >> 9;
    int k2 = idx & 511;
    int j = n >> 2, g = n & 3;
    const float *U, *V, *bb;
    if (g == 0)      { U = Ui; V = Vi; bb = bi; }
    else if (g == 1) { U = Uf; V = Vf; bb = bf; }
    else if (g == 2) { U = Uc; V = Vc; bb = bc; }
    else             { U = Uo; V = Vo; bb = bo; }
    const float* Up = U + (size_t)j * HIDN + 2 * k2;
    const float* Vp = V + (size_t)j * HIDN + 2 * k2;
    g_Ub[idx] = pack_bf2(Up[0], Up[1]);
    g_Vb[idx] = pack_bf2(Vp[0], Vp[1]);
    if (k2 == 0) g_ball[n] = bb[j];
    if (idx < BATCH * (HIDN / 2)) {
        g_hb[0][idx] = pack_bf2(h0[2 * idx], h0[2 * idx + 1]);
        float2 hv; hv.x = h0[2 * idx]; hv.y = h0[2 * idx + 1];
        *(float2*)&g_h[0][2 * idx] = hv;
        float2 cv; cv.x = c0[2 * idx]; cv.y = c0[2 * idx + 1];
        *(float2*)&g_c[2 * idx] = cv;
    }
}

// ---------------- pack emb -> bf16 ----------------
__global__ void pack_emb_kernel(const float* __restrict__ emb)
{
    size_t idx = (size_t)blockIdx.x * blockDim.x + threadIdx.x;
    if (idx >= (size_t)NCLS * (EMBD / 2)) return;
    g_Eb[idx] = pack_bf2(emb[2 * idx], emb[2 * idx + 1]);
}

// ---------------- fused persistent kernel: input GEMM + recurrent GEMM + cell ----------------
// 128 CTAs, 256 threads. Per step t each CTA computes:
//   racc = h[t] @ V^T   (V resident in smem)
//   zacc = emb[X[:,t+1]] @ U^T  (U/emb streamed; result kept in regs as zprev)
// Epilogue: gates = racc + zprev(t), LSTM cell, h out. Zin never touches global memory.
#define STG_H (128 * 20)
#define STG_E (128 * 20)
#define STG_U (64 * 20)
#define SMEM_P_WORDS (64 * VSTR + 2 * STG_H + 2 * STG_E + 2 * STG_U)
#define SMEM_P_BYTES (SMEM_P_WORDS * 4)   /* 183296 */

__global__ __launch_bounds__(PTHREADS, 1)
void lstm_fused_kernel(const int* __restrict__ Xids)
{
    extern __shared__ unsigned smem[];
    unsigned* smV = smem;                          // resident V slice
    unsigned* smH = smem + 64 * VSTR;              // 2 x 128x20 h staging
    unsigned* smE = smH + 2 * STG_H;               // 2 x 128x20 emb staging
    unsigned* smU = smE + 2 * STG_E;               // 2 x 64x20 U staging
    float*    smG = (float*)smH;                   // gate tile, overlays staging

    const int tid  = threadIdx.x;
    const int lane = tid & 31;
    const int warp = tid >> 5;
    const int wm = (warp >> 1) * 32;
    const int wn = (warp & 1) * 32;
    const int bid = blockIdx.x;
    const int m0  = (bid & 1) * 128;
    const int nsl = bid >> 1;
    const int n0  = nsl * 64;

    // one-time: resident V slice
    for (int i = tid; i < 64 * 128; i += PTHREADS) {
        int n = i >> 7, k4 = (i & 127) * 4;
        *(uint4*)&smV[n * VSTR + k4] = *(const uint4*)&g_Vb[(size_t)(n0 + n) * 512 + k4];
    }

    // one-time: c slice into registers
    float creg[4][2];
#pragma unroll
    for (int it = 0; it < 4; it++) {
        int idx = tid + it * PTHREADS;
        int lr = idx >> 3, jp = idx & 7;
        float2 cv = *(const float2*)&g_c[(m0 + lr) * HIDN + nsl * 16 + jp * 2];
        creg[it][0] = cv.x; creg[it][1] = cv.y;
    }

    // one-time: bias for this thread's epilogue columns (jp = tid & 7 is it-invariant)
    float bb[8];
    {
        const float* bp = &g_ball[n0 + (tid & 7) * 8];
        float4 x0 = *(const float4*)bp;
        float4 x1 = *(const float4*)(bp + 4);
        bb[0] = x0.x; bb[1] = x0.y; bb[2] = x0.z; bb[3] = x0.w;
        bb[4] = x1.x; bb[5] = x1.y; bb[6] = x1.z; bb[7] = x1.w;
    }

    const int kcol  = (tid & 3) * 4;
    const int ldrow = tid >> 2;           // 0..63
    const int r0 = m0 + ldrow, r1 = r0 + 64;
    const unsigned* urp = g_Ub + (size_t)(n0 + ldrow) * 512 + kcol;

    float zprev[4][8];
    __syncthreads();

    // ---------------- prologue: Z(0) = emb[X[:,0]] @ U^T ----------------
    {
        int v0 = Xids[r0 * SEQL + 0];
        int v1 = Xids[r1 * SEQL + 0];
        const unsigned* ep0 = g_Eb + (size_t)v0 * 512 + kcol;
        const unsigned* ep1 = g_Eb + (size_t)v1 * 512 + kcol;

        float zacc[2][4][4];
#pragma unroll
        for (int a = 0; a < 2; a++)
#pragma unroll
            for (int b_ = 0; b_ < 4; b_++)
#pragma unroll
                for (int c_ = 0; c_ < 4; c_++) zacc[a][b_][c_] = 0.f;

        uint4 e0 = *(const uint4*)ep0;
        uint4 e1 = *(const uint4*)ep1;
        uint4 u0 = *(const uint4*)urp;
        *(uint4*)&smE[ldrow * 20 + kcol]        = e0;
        *(uint4*)&smE[(ldrow + 64) * 20 + kcol] = e1;
        *(uint4*)&smU[ldrow * 20 + kcol]        = u0;
        __syncthreads();

        for (int kc = 0; kc < 32; kc++) {
            const int cur = kc & 1;
            if (kc + 1 < 32) {
                e0 = *(const uint4*)(ep0 + (kc + 1) * 16);
                e1 = *(const uint4*)(ep1 + (kc + 1) * 16);
                u0 = *(const uint4*)(urp + (kc + 1) * 16);
            }
            const unsigned* Es = smE + cur * STG_E;
            const unsigned* Us = smU + cur * STG_U;
#pragma unroll
            for (int ks = 0; ks < 2; ks++) {
                unsigned ae[2][4], bu[4][2];
#pragma unroll
                for (int mt = 0; mt < 2; mt++) {
                    const unsigned* ap = &Es[(wm + mt * 16 + (lane >> 2)) * 20 + ks * 8 + (lane & 3)];
                    ae[mt][0] = ap[0]; ae[mt][1] = ap[8 * 20]; ae[mt][2] = ap[4]; ae[mt][3] = ap[8 * 20 + 4];
                }
#pragma unroll
                for (int nt = 0; nt < 4; nt++) {
                    const unsigned* bp = &Us[(wn + nt * 8 + (lane >> 2)) * 20 + ks * 8 + (lane & 3)];
                    bu[nt][0] = bp[0]; bu[nt][1] = bp[4];
                }
#pragma unroll
                for (int mt = 0; mt < 2; mt++)
#pragma unroll
                    for (int nt = 0; nt < 4; nt++)
                        mma_bf16(zacc[mt][nt], ae[mt], bu[nt]);
            }
            if (kc + 1 < 32) {
                unsigned* Ed = smE + ((kc + 1) & 1) * STG_E;
                unsigned* Ud = smU + ((kc + 1) & 1) * STG_U;
                *(uint4*)&Ed[ldrow * 20 + kcol]        = e0;
                *(uint4*)&Ed[(ldrow + 64) * 20 + kcol] = e1;
                *(uint4*)&Ud[ldrow * 20 + kcol]        = u0;
            }
            __syncthreads();
        }

        // round-trip zacc -> epilogue layout
#pragma unroll
        for (int mt = 0; mt < 2; mt++)
#pragma unroll
            for (int nt = 0; nt < 4; nt++) {
                int lr = wm + mt * 16 + (lane >> 2);
                int lc = wn + nt * 8 + (lane & 3) * 2;
                smG[lr * GS + lc]           = zacc[mt][nt][0];
                smG[lr * GS + lc + 1]       = zacc[mt][nt][1];
                smG[(lr + 8) * GS + lc]     = zacc[mt][nt][2];
                smG[(lr + 8) * GS + lc + 1] = zacc[mt][nt][3];
            }
        __syncthreads();
#pragma unroll
        for (int it = 0; it < 4; it++) {
            int idx = tid + it * PTHREADS;
            int lr = idx >> 3, jp = idx & 7;
            const float* Gp = &smG[lr * GS + jp * 8];
#pragma unroll
            for (int q = 0; q < 8; q++) zprev[it][q] = Gp[q] + bb[q];
        }
        __syncthreads();
    }

    // ---------------- main loop ----------------
    for (int t = 0; t < SEQL; t++) {
        const int tn = (t + 1 < SEQL) ? (t + 1) : (SEQL - 1);
        int v0 = Xids[r0 * SEQL + tn];
        int v1 = Xids[r1 * SEQL + tn];
        const unsigned* ep0 = g_Eb + (size_t)v0 * 512 + kcol;
        const unsigned* ep1 = g_Eb + (size_t)v1 * 512 + kcol;
        const unsigned* hin = g_hb[t & 1];
        const unsigned* hp0 = hin + (size_t)r0 * 512 + kcol;
        const unsigned* hp1 = hin + (size_t)r1 * 512 + kcol;

        float racc[2][4][4], zacc[2][4][4];
#pragma unroll
        for (int a = 0; a < 2; a++)
#pragma unroll
            for (int b_ = 0; b_ < 4; b_++)
#pragma unroll
                for (int c_ = 0; c_ < 4; c_++) { racc[a][b_][c_] = 0.f; zacc[a][b_][c_] = 0.f; }

        uint4 h0r = *(const uint4*)hp0;
        uint4 h1r = *(const uint4*)hp1;
        uint4 e0  = *(const uint4*)ep0;
        uint4 e1  = *(const uint4*)ep1;
        uint4 u0  = *(const uint4*)urp;
        *(uint4*)&smH[ldrow * 20 + kcol]        = h0r;
        *(uint4*)&smH[(ldrow + 64) * 20 + kcol] = h1r;
        *(uint4*)&smE[ldrow * 20 + kcol]        = e0;
        *(uint4*)&smE[(ldrow + 64) * 20 + kcol] = e1;
        *(uint4*)&smU[ldrow * 20 + kcol]        = u0;
        __syncthreads();

        for (int kc = 0; kc < 32; kc++) {
            const int cur = kc & 1;
            if (kc + 1 < 32) {
                h0r = *(const uint4*)(hp0 + (kc + 1) * 16);
                h1r = *(const uint4*)(hp1 + (kc + 1) * 16);
                e0  = *(const uint4*)(ep0 + (kc + 1) * 16);
                e1  = *(const uint4*)(ep1 + (kc + 1) * 16);
                u0  = *(const uint4*)(urp + (kc + 1) * 16);
            }
            const unsigned* Hs = smH + cur * STG_H;
            const unsigned* Es = smE + cur * STG_E;
            const unsigned* Us = smU + cur * STG_U;
#pragma unroll
            for (int ks = 0; ks < 2; ks++) {
                // recurrent: A = h (staged), B = V (resident)
                unsigned ah[2][4], bv[4][2];
#pragma unroll
                for (int mt = 0; mt < 2; mt++) {
                    const unsigned* ap = &Hs[(wm + mt * 16 + (lane >> 2)) * 20 + ks * 8 + (lane & 3)];
                    ah[mt][0] = ap[0]; ah[mt][1] = ap[8 * 20]; ah[mt][2] = ap[4]; ah[mt][3] = ap[8 * 20 + 4];
                }
#pragma unroll
                for (int nt = 0; nt < 4; nt++) {
                    const unsigned* bp = &smV[(wn + nt * 8 + (lane >> 2)) * VSTR + kc * 16 + ks * 8 + (lane & 3)];
                    bv[nt][0] = bp[0]; bv[nt][1] = bp[4];
                }
#pragma unroll
                for (int mt = 0; mt < 2; mt++)
#pragma unroll
                    for (int nt = 0; nt < 4; nt++)
                        mma_bf16(racc[mt][nt], ah[mt], bv[nt]);

                // input: A = emb (staged), B = U (staged)
                unsigned ae[2][4], bu[4][2];
#pragma unroll
                for (int mt = 0; mt < 2; mt++) {
                    const unsigned* ap = &Es[(wm + mt * 16 + (lane >> 2)) * 20 + ks * 8 + (lane & 3)];
                    ae[mt][0] = ap[0]; ae[mt][1] = ap[8 * 20]; ae[mt][2] = ap[4]; ae[mt][3] = ap[8 * 20 + 4];
                }
#pragma unroll
                for (int nt = 0; nt < 4; nt++) {
                    const unsigned* bp = &Us[(wn + nt * 8 + (lane >> 2)) * 20 + ks * 8 + (lane & 3)];
                    bu[nt][0] = bp[0]; bu[nt][1] = bp[4];
                }
#pragma unroll
                for (int mt = 0; mt < 2; mt++)
#pragma unroll
                    for (int nt = 0; nt < 4; nt++)
                        mma_bf16(zacc[mt][nt], ae[mt], bu[nt]);
            }
            if (kc + 1 < 32) {
                const int nxt = (kc + 1) & 1;
                unsigned* Hd = smH + nxt * STG_H;
                unsigned* Ed = smE + nxt * STG_E;
                unsigned* Ud = smU + nxt * STG_U;
                *(uint4*)&Hd[ldrow * 20 + kcol]        = h0r;
                *(uint4*)&Hd[(ldrow + 64) * 20 + kcol] = h1r;
                *(uint4*)&Ed[ldrow * 20 + kcol]        = e0;
                *(uint4*)&Ed[(ldrow + 64) * 20 + kcol] = e1;
                *(uint4*)&Ud[ldrow * 20 + kcol]        = u0;
            }
            __syncthreads();
        }

        // racc round-trip + fused LSTM cell
#pragma unroll
        for (int mt = 0; mt < 2; mt++)
#pragma unroll
            for (int nt = 0; nt < 4; nt++) {
                int lr = wm + mt * 16 + (lane >> 2);
                int lc = wn + nt * 8 + (lane & 3) * 2;
                smG[lr * GS + lc]           = racc[mt][nt][0];
                smG[lr * GS + lc + 1]       = racc[mt][nt][1];
                smG[(lr + 8) * GS + lc]     = racc[mt][nt][2];
                smG[(lr + 8) * GS + lc + 1] = racc[mt][nt][3];
            }
        __syncthreads();

        unsigned* hbout = g_hb[(t & 1) ^ 1];
#pragma unroll
        for (int it = 0; it < 4; it++) {
            int idx = tid + it * PTHREADS;
            int lr = idx >> 3, jp = idx & 7;
            int m = m0 + lr;
            const float* Gp = &smG[lr * GS + jp * 8];

            float i0 = fsig(Gp[0] + zprev[it][0]);
            float f0 = fsig(Gp[1] + zprev[it][1]);
            float g0 = tanhf(Gp[2] + zprev[it][2]);
            float o0 = fsig(Gp[3] + zprev[it][3]);
            float i1 = fsig(Gp[4] + zprev[it][4]);
            float f1 = fsig(Gp[5] + zprev[it][5]);
            float g1 = tanhf(Gp[6] + zprev[it][6]);
            float o1 = fsig(Gp[7] + zprev[it][7]);

            float cn0 = f0 * creg[it][0] + i0 * g0;
            float cn1 = f1 * creg[it][1] + i1 * g1;
            creg[it][0] = cn0; creg[it][1] = cn1;

            float h0v = o0 * tanhf(cn0);
            float h1v = o1 * tanhf(cn1);
            hbout[m * 512 + nsl * 8 + jp] = pack_bf2(h0v, h1v);
            if (t == SEQL - 1) {
                float2 hf; hf.x = h0v; hf.y = h1v;
                *(float2*)&g_h[0][m * HIDN + nsl * 16 + jp * 2] = hf;
            }
        }
        __syncthreads();

        // zacc round-trip -> zprev for step t+1 (includes bias)
#pragma unroll
        for (int mt = 0; mt < 2; mt++)
#pragma unroll
            for (int nt = 0; nt < 4; nt++) {
                int lr = wm + mt * 16 + (lane >> 2);
                int lc = wn + nt * 8 + (lane & 3) * 2;
                smG[lr * GS + lc]           = zacc[mt][nt][0];
                smG[lr * GS + lc + 1]       = zacc[mt][nt][1];
                smG[(lr + 8) * GS + lc]     = zacc[mt][nt][2];
                smG[(lr + 8) * GS + lc + 1] = zacc[mt][nt][3];
            }
        __syncthreads();
#pragma unroll
        for (int it = 0; it < 4; it++) {
            int idx = tid + it * PTHREADS;
            int lr = idx >> 3, jp = idx & 7;
            const float* Gp = &smG[lr * GS + jp * 8];
#pragma unroll
            for (int q = 0; q < 8; q++) zprev[it][q] = Gp[q] + bb[q];
        }

        // grid barrier between steps (also orders smG reads before next staging writes)
        if (t < SEQL - 1) {
            __syncthreads();
            if (tid == 0) {
                __threadfence();
                atomicAdd(&g_bar, 1u);
                const unsigned target = (unsigned)NCTA * (t + 1);
                unsigned v;
                do {
                    asm volatile("ld.acquire.gpu.u32 %0, [%1];"
                                 : "=r"(v) : "l"(&g_bar) : "memory");
                } while (v < target);
            }
            __syncthreads();
        }
    }
}

// ---------------- tf32 output projection: out = h_final @ W^T + b ----------------
__global__ __launch_bounds__(128)
void out_gemm_kernel(const float* __restrict__ W,
                     const float* __restrict__ biasp,
                     float* __restrict__ Cout)
{
    const int tid  = threadIdx.x;
    const int lane = tid & 31;
    const int warp = tid >> 5;
    const int wm = (warp >> 1) * 64;
    const int wn = (warp & 1) * 32;
    const int n0 = blockIdx.x * BN;
    const int m0 = blockIdx.y * BM;

    __shared__ struct { float A[2][BM * AS]; float B[2][BN * BSS]; } sm;

    const float* Ain = g_h[0];
    const int kcol  = (tid & 3) * 4;
    const int ldrow = tid >> 2;

    const float* arp[4];
#pragma unroll
    for (int i = 0; i < 4; i++)
        arp[i] = Ain + (size_t)(m0 + ldrow + 32 * i) * HIDN + kcol;
    const float* brp[2];
#pragma unroll
    for (int i = 0; i < 2; i++)
        brp[i] = W + (size_t)(n0 + ldrow + 32 * i) * HIDN + kcol;

    float4 areg[4], breg[2];
    float acc[4][4][4];
#pragma unroll
    for (int a = 0; a < 4; a++)
#pragma unroll
        for (int b_ = 0; b_ < 4; b_++)
#pragma unroll
            for (int c_ = 0; c_ < 4; c_++) acc[a][b_][c_] = 0.f;

#pragma unroll
    for (int i = 0; i < 4; i++) areg[i] = *(const float4*)(arp[i]);
#pragma unroll
    for (int i = 0; i < 2; i++) breg[i] = *(const float4*)(brp[i]);
#pragma unroll
    for (int i = 0; i < 4; i++) {
        float4 v = areg[i];
        v.x = f2tf32(v.x); v.y = f2tf32(v.y); v.z = f2tf32(v.z); v.w = f2tf32(v.w);
        *(float4*)&sm.A[0][(ldrow + 32 * i) * AS + kcol] = v;
    }
#pragma unroll
    for (int i = 0; i < 2; i++) {
        float4 v = breg[i];
        v.x = f2tf32(v.x); v.y = f2tf32(v.y); v.z = f2tf32(v.z); v.w = f2tf32(v.w);
        *(float4*)&sm.B[0][(ldrow + 32 * i) * BSS + kcol] = v;
    }
    __syncthreads();

    const int NCH = HIDN / BK;
    for (int kc = 0; kc < NCH; kc++) {
        int cur = kc & 1;
        if (kc + 1 < NCH) {
#pragma unroll
            for (int i = 0; i < 4; i++) areg[i] = *(const float4*)(arp[i] + (kc + 1) * BK);
#pragma unroll
            for (int i = 0; i < 2; i++) breg[i] = *(const float4*)(brp[i] + (kc + 1) * BK);
        }
#pragma unroll
        for (int k8 = 0; k8 < BK; k8 += 8) {
            uint32_t af[4][4], bfr[4][2];
#pragma unroll
            for (int mt = 0; mt < 4; mt++) {
                const float* ap = &sm.A[cur][(wm + mt * 16 + (lane >> 2)) * AS + k8 + (lane & 3)];
                af[mt][0] = __float_as_uint(ap[0]);
                af[mt][1] = __float_as_uint(ap[8 * AS]);
                af[mt][2] = __float_as_uint(ap[4]);
                af[mt][3] = __float_as_uint(ap[8 * AS + 4]);
            }
#pragma unroll
            for (int nt = 0; nt < 4; nt++) {
                const float* bp = &sm.B[cur][(wn + nt * 8 + (lane >> 2)) * BSS + k8 + (lane & 3)];
                bfr[nt][0] = __float_as_uint(bp[0]);
                bfr[nt][1] = __float_as_uint(bp[4]);
            }
#pragma unroll
            for (int mt = 0; mt < 4; mt++)
#pragma unroll
                for (int nt = 0; nt < 4; nt++)
                    asm volatile(
                        "mma.sync.aligned.m16n8k8.row.col.f32.tf32.tf32.f32 "
                        "{%0,%1,%2,%3}, {%4,%5,%6,%7}, {%8,%9}, {%0,%1,%2,%3};"
                        : "+f"(acc[mt][nt][0]), "+f"(acc[mt][nt][1]),
                          "+f"(acc[mt][nt][2]), "+f"(acc[mt][nt][3])
                        : "r"(af[mt][0]), "r"(af[mt][1]), "r"(af[mt][2]), "r"(af[mt][3]),
                          "r"(bfr[nt][0]), "r"(bfr[nt][1]));
        }
        if (kc + 1 < NCH) {
            int nxt = cur ^ 1;
#pragma unroll
            for (int i = 0; i < 4; i++) {
                float4 v = areg[i];
                v.x = f2tf32(v.x); v.y = f2tf32(v.y); v.z = f2tf32(v.z); v.w = f2tf32(v.w);
                *(float4*)&sm.A[nxt][(ldrow + 32 * i) * AS + kcol] = v;
            }
#pragma unroll
            for (int i = 0; i < 2; i++) {
                float4 v = breg[i];
                v.x = f2tf32(v.x); v.y = f2tf32(v.y); v.z = f2tf32(v.z); v.w = f2tf32(v.w);
                *(float4*)&sm.B[nxt][(ldrow + 32 * i) * BSS + kcol] = v;
            }
        }
        __syncthreads();
    }

#pragma unroll
    for (int mt = 0; mt < 4; mt++) {
#pragma unroll
        for (int nt = 0; nt < 4; nt++) {
            int r = m0 + wm + mt * 16 + (lane >> 2);
            int cidx = n0 + wn + nt * 8 + (lane & 3) * 2;
            float2 bv = *(const float2*)&biasp[cidx];
            float2 v0; v0.x = acc[mt][nt][0] + bv.x; v0.y = acc[mt][nt][1] + bv.y;
            float2 v1; v1.x = acc[mt][nt][2] + bv.x; v1.y = acc[mt][nt][3] + bv.y;
            *(float2*)&Cout[(size_t)r * NCLS + cidx] = v0;
            *(float2*)&Cout[(size_t)(r + 8) * NCLS + cidx] = v1;
        }
    }
}

// ---------------- launch ----------------
extern "C" void kernel_launch(void* const* d_in, const int* in_sizes, int n_in,
                              void* d_out, int out_size)
{
    const int*   X   = (const int*)  d_in[0];
    const float* h0  = (const float*)d_in[1];
    const float* c0  = (const float*)d_in[2];
    const float* emb = (const float*)d_in[3];
    const float* Ui  = (const float*)d_in[4];
    const float* Vi  = (const float*)d_in[5];
    const float* bi  = (const float*)d_in[6];
    const float* Uf  = (const float*)d_in[7];
    const float* Vf  = (const float*)d_in[8];
    const float* bf  = (const float*)d_in[9];
    const float* Uc  = (const float*)d_in[10];
    const float* Vc  = (const float*)d_in[11];
    const float* bc  = (const float*)d_in[12];
    const float* Uo  = (const float*)d_in[13];
    const float* Vo  = (const float*)d_in[14];
    const float* bo  = (const float*)d_in[15];
    const float* W   = (const float*)d_in[16];
    const float* b   = (const float*)d_in[17];
    float* out = (float*)d_out;

    cudaFuncSetAttribute(lstm_fused_kernel,
                         cudaFuncAttributeMaxDynamicSharedMemorySize, SMEM_P_BYTES);

    // 1) pack weights (bf16 interleaved), biases, init state, reset barrier
    pack_kernel<<<(NG * (HIDN / 2) + 255) / 256, 256>>>(Ui, Vi, bi, Uf, Vf, bf,
                                                        Uc, Vc, bc, Uo, Vo, bo, h0, c0);
    pack_emb_kernel<<<(int)(((size_t)NCLS * (EMBD / 2) + 255) / 256), 256>>>(emb);

    // 2) fused persistent kernel: input GEMM + 128 recurrent steps, Zin in registers
    lstm_fused_kernel<<<NCTA, PTHREADS, SMEM_P_BYTES>>>(X);

    // 3) output projection (tf32): out = h_final @ W^T + b
    out_gemm_kernel<<<dim3(NCLS / BN, BATCH / BM), 128>>>(W, b, out);
}

// round 7
// speedup vs baseline: 1.4270x; 1.4270x over previous
#include <cuda_runtime.h>
#include <cuda_bf16.h>
#include <cstdint>
#include <cmath>

#define HIDN 1024
#define EMBD 1024
#define BATCH 256
#define SEQL 128
#define NCLS 32000
#define NG   4096   /* 4*HIDN, gate-interleaved: n = 4*j + g */

#define BM 128
#define BN 64
#define BK 16
#define AS 20
#define BSS 20
#define GS 68
#define VSTR 516
#define ASTR 36          /* steps A-stage stride (u32), 4*row mod 32 distinct -> conflict-free */
#define STG_A (128 * ASTR)

#define NCTA 128
#define PTHREADS 256

// ---------------- device scratch (no allocations allowed) ----------------
static __device__ unsigned g_Ub[NG * (HIDN / 2)];            // 8 MB interleaved U, bf16x2
static __device__ unsigned g_Vb[NG * (HIDN / 2)];            // 8 MB interleaved V, bf16x2
static __device__ unsigned g_Eb[(size_t)NCLS * (EMBD / 2)];  // 64 MB emb, bf16x2
static __device__ float    g_ball[NG];
static __device__ float    g_Zin[(size_t)SEQL * BATCH * NG]; // 512 MB input-side gates
static __device__ float    g_h[2][BATCH * HIDN];             // fp32 h (final proj reads [0])
static __device__ unsigned g_hb[2][BATCH * (HIDN / 2)];      // bf16x2 h ping-pong
static __device__ float    g_c[BATCH * HIDN];
static __device__ unsigned g_bar;                            // grid barrier

// ---------------- helpers ----------------
__device__ __forceinline__ float f2tf32(float x) {
    uint32_t r;
    asm("cvt.rna.tf32.f32 %0, %1;" : "=r"(r) : "f"(x));
    return __uint_as_float(r);
}
__device__ __forceinline__ unsigned pack_bf2(float a, float b) {
    __nv_bfloat162 v = __floats2bfloat162_rn(a, b);
    return *reinterpret_cast<unsigned*>(&v);
}
__device__ __forceinline__ float fsig(float x) {
    return __fdividef(1.f, 1.f + __expf(-x));
}
__device__ __forceinline__ void mma_bf16(float* acc, const unsigned* a, const unsigned* b) {
    asm volatile(
        "mma.sync.aligned.m16n8k16.row.col.f32.bf16.bf16.f32 "
        "{%0,%1,%2,%3}, {%4,%5,%6,%7}, {%8,%9}, {%0,%1,%2,%3};"
        : "+f"(acc[0]), "+f"(acc[1]), "+f"(acc[2]), "+f"(acc[3])
        : "r"(a[0]), "r"(a[1]), "r"(a[2]), "r"(a[3]), "r"(b[0]), "r"(b[1]));
}

// ---------------- pack: interleave U/V (bf16), biases, init state ----------------
__global__ void pack_kernel(const float* __restrict__ Ui, const float* __restrict__ Vi, const float* __restrict__ bi,
                            const float* __restrict__ Uf, const float* __restrict__ Vf, const float* __restrict__ bf,
                            const float* __restrict__ Uc, const float* __restrict__ Vc, const float* __restrict__ bc,
                            const float* __restrict__ Uo, const float* __restrict__ Vo, const float* __restrict__ bo,
                            const float* __restrict__ h0, const float* __restrict__ c0)
{
    int idx = blockIdx.x * blockDim.x + threadIdx.x;
    if (idx >= NG * (HIDN / 2)) return;
    if (idx == 0) g_bar = 0u;
    int n = idx >> 9;
    int k2 = idx & 511;
    int j = n >> 2, g = n & 3;
    const float *U, *V, *bb;
    if (g == 0)      { U = Ui; V = Vi; bb = bi; }
    else if (g == 1) { U = Uf; V = Vf; bb = bf; }
    else if (g == 2) { U = Uc; V = Vc; bb = bc; }
    else             { U = Uo; V = Vo; bb = bo; }
    const float* Up = U + (size_t)j * HIDN + 2 * k2;
    const float* Vp = V + (size_t)j * HIDN + 2 * k2;
    g_Ub[idx] = pack_bf2(Up[0], Up[1]);
    g_Vb[idx] = pack_bf2(Vp[0], Vp[1]);
    if (k2 == 0) g_ball[n] = bb[j];
    if (idx < BATCH * (HIDN / 2)) {
        g_hb[0][idx] = pack_bf2(h0[2 * idx], h0[2 * idx + 1]);
        float2 hv; hv.x = h0[2 * idx]; hv.y = h0[2 * idx + 1];
        *(float2*)&g_h[0][2 * idx] = hv;
        float2 cv; cv.x = c0[2 * idx]; cv.y = c0[2 * idx + 1];
        *(float2*)&g_c[2 * idx] = cv;
    }
}

__global__ void pack_emb_kernel(const float* __restrict__ emb)
{
    size_t idx = (size_t)blockIdx.x * blockDim.x + threadIdx.x;
    if (idx >= (size_t)NCLS * (EMBD / 2)) return;
    g_Eb[idx] = pack_bf2(emb[2 * idx], emb[2 * idx + 1]);
}

// ---------------- bf16 input GEMM: Zin = gather(emb,X) @ Uall^T + ball ----------------
// grid (32, 256), 256 threads, CTA tile 128x128, warp tile 64x32 (16 mma / 24 LDS per ks)
__global__ __launch_bounds__(256, 2)
void input_gemm_kernel(const int* __restrict__ Xids)
{
    const int tid  = threadIdx.x;
    const int lane = tid & 31;
    const int warp = tid >> 5;
    const int wm = (warp >> 2) * 64;   // 2 m-warps x 64 rows
    const int wn = (warp & 3) * 32;    // 4 n-warps x 32 cols
    const int n0 = blockIdx.x * 128;
    const int m0 = blockIdx.y * 128;

    __shared__ unsigned smA[2][128 * 20];
    __shared__ unsigned smB[2][128 * 20];
    __shared__ int vrow[128];

    if (tid < 128) {
        int r = m0 + tid;
        vrow[tid] = Xids[(r & 255) * SEQL + (r >> 8)];
    }
    __syncthreads();

    const int kcol  = (tid & 3) * 4;
    const int ldrow = tid >> 2;     // 0..63

    const unsigned* ap0 = g_Eb + (size_t)vrow[ldrow] * 512 + kcol;
    const unsigned* ap1 = g_Eb + (size_t)vrow[ldrow + 64] * 512 + kcol;
    const unsigned* bp0 = g_Ub + (size_t)(n0 + ldrow) * 512 + kcol;
    const unsigned* bp1 = g_Ub + (size_t)(n0 + ldrow + 64) * 512 + kcol;

    float acc[4][4][4];
#pragma unroll
    for (int a = 0; a < 4; a++)
#pragma unroll
        for (int b_ = 0; b_ < 4; b_++)
#pragma unroll
            for (int c_ = 0; c_ < 4; c_++) acc[a][b_][c_] = 0.f;

    uint4 a0 = *(const uint4*)ap0;
    uint4 a1 = *(const uint4*)ap1;
    uint4 b0 = *(const uint4*)bp0;
    uint4 b1 = *(const uint4*)bp1;
    *(uint4*)&smA[0][ldrow * 20 + kcol]        = a0;
    *(uint4*)&smA[0][(ldrow + 64) * 20 + kcol] = a1;
    *(uint4*)&smB[0][ldrow * 20 + kcol]        = b0;
    *(uint4*)&smB[0][(ldrow + 64) * 20 + kcol] = b1;
    __syncthreads();

    for (int kc = 0; kc < 32; kc++) {
        const int cur = kc & 1;
        if (kc + 1 < 32) {
            a0 = *(const uint4*)(ap0 + (kc + 1) * 16);
            a1 = *(const uint4*)(ap1 + (kc + 1) * 16);
            b0 = *(const uint4*)(bp0 + (kc + 1) * 16);
            b1 = *(const uint4*)(bp1 + (kc + 1) * 16);
        }
#pragma unroll
        for (int ks = 0; ks < 2; ks++) {
            unsigned af[4][4], bfr[4][2];
#pragma unroll
            for (int mt = 0; mt < 4; mt++) {
                const unsigned* ap = &smA[cur][(wm + mt * 16 + (lane >> 2)) * 20 + ks * 8 + (lane & 3)];
                af[mt][0] = ap[0]; af[mt][1] = ap[8 * 20]; af[mt][2] = ap[4]; af[mt][3] = ap[8 * 20 + 4];
            }
#pragma unroll
            for (int nt = 0; nt < 4; nt++) {
                const unsigned* bp = &smB[cur][(wn + nt * 8 + (lane >> 2)) * 20 + ks * 8 + (lane & 3)];
                bfr[nt][0] = bp[0]; bfr[nt][1] = bp[4];
            }
#pragma unroll
            for (int mt = 0; mt < 4; mt++)
#pragma unroll
                for (int nt = 0; nt < 4; nt++)
                    mma_bf16(acc[mt][nt], af[mt], bfr[nt]);
        }
        if (kc + 1 < 32) {
            const int nxt = (kc + 1) & 1;
            *(uint4*)&smA[nxt][ldrow * 20 + kcol]        = a0;
            *(uint4*)&smA[nxt][(ldrow + 64) * 20 + kcol] = a1;
            *(uint4*)&smB[nxt][ldrow * 20 + kcol]        = b0;
            *(uint4*)&smB[nxt][(ldrow + 64) * 20 + kcol] = b1;
        }
        __syncthreads();
    }

    // epilogue: + bias, store fp32 Zin (row-major [r][n])
#pragma unroll
    for (int mt = 0; mt < 4; mt++) {
#pragma unroll
        for (int nt = 0; nt < 4; nt++) {
            int r = m0 + wm + mt * 16 + (lane >> 2);
            int cidx = n0 + wn + nt * 8 + (lane & 3) * 2;
            float2 bv = *(const float2*)&g_ball[cidx];
            float2 o0; o0.x = acc[mt][nt][0] + bv.x; o0.y = acc[mt][nt][1] + bv.y;
            float2 o1; o1.x = acc[mt][nt][2] + bv.x; o1.y = acc[mt][nt][3] + bv.y;
            *(float2*)&g_Zin[(size_t)r * NG + cidx] = o0;
            *(float2*)&g_Zin[(size_t)(r + 8) * NG + cidx] = o1;
        }
    }
}

// ---------------- persistent recurrent kernel (R4 structure, K-chunk 32 half2) ----------------
#define SMEM_P_BYTES ((64 * VSTR) * 4 + 2 * STG_A * 4)   /* G tile (34816B) < A stage (36864B) */

__global__ __launch_bounds__(PTHREADS, 1)
void lstm_persistent_kernel()
{
    extern __shared__ unsigned smem[];
    unsigned* smV = smem;
    unsigned* smA = smem + 64 * VSTR;
    float*    smG = (float*)(smem + 64 * VSTR);

    const int tid  = threadIdx.x;
    const int lane = tid & 31;
    const int warp = tid >> 5;
    const int wm = (warp >> 1) * 32;
    const int wn = (warp & 1) * 32;
    const int bid = blockIdx.x;
    const int m0  = (bid & 1) * 128;
    const int nsl = bid >> 1;
    const int n0  = nsl * 64;

    for (int i = tid; i < 64 * 128; i += PTHREADS) {
        int n = i >> 7, k4 = (i & 127) * 4;
        *(uint4*)&smV[n * VSTR + k4] = *(const uint4*)&g_Vb[(size_t)(n0 + n) * 512 + k4];
    }

    float creg[4][2];
#pragma unroll
    for (int it = 0; it < 4; it++) {
        int idx = tid + it * PTHREADS;
        int lr = idx >> 3, jp = idx & 7;
        float2 cv = *(const float2*)&g_c[(m0 + lr) * HIDN + nsl * 16 + jp * 2];
        creg[it][0] = cv.x; creg[it][1] = cv.y;
    }

    const int kcol  = (tid & 3) * 4;
    const int ldrow = tid >> 2;
    __syncthreads();

    for (int t = 0; t < SEQL; t++) {
        // prefetch this step's Zin slice early (MLP=8, hidden behind the GEMM)
        float4 zpre[4][2];
#pragma unroll
        for (int it = 0; it < 4; it++) {
            int idx = tid + it * PTHREADS;
            int lr = idx >> 3, jp = idx & 7;
            size_t zb = ((size_t)t * BATCH + m0 + lr) * NG + n0 + jp * 8;
            zpre[it][0] = *(const float4*)&g_Zin[zb];
            zpre[it][1] = *(const float4*)&g_Zin[zb + 4];
        }

        const unsigned* hin = g_hb[t & 1];
        const unsigned* arp0 = hin + (size_t)(m0 + ldrow) * 512 + kcol;
        const unsigned* arp1 = hin + (size_t)(m0 + ldrow + 64) * 512 + kcol;

        float acc[2][4][4];
#pragma unroll
        for (int a = 0; a < 2; a++)
#pragma unroll
            for (int b_ = 0; b_ < 4; b_++)
#pragma unroll
                for (int c_ = 0; c_ < 4; c_++) acc[a][b_][c_] = 0.f;

        // K-chunk = 32 half2 (64 bf16), 16 iterations; per-thread 4 uint4 per chunk
        uint4 a00 = *(const uint4*)arp0;
        uint4 a01 = *(const uint4*)(arp0 + 16);
        uint4 a10 = *(const uint4*)arp1;
        uint4 a11 = *(const uint4*)(arp1 + 16);
        *(uint4*)&smA[ldrow * ASTR + kcol]             = a00;
        *(uint4*)&smA[ldrow * ASTR + kcol + 16]        = a01;
        *(uint4*)&smA[(ldrow + 64) * ASTR + kcol]      = a10;
        *(uint4*)&smA[(ldrow + 64) * ASTR + kcol + 16] = a11;
        __syncthreads();

        for (int kc = 0; kc < 16; kc++) {
            const int cur = kc & 1;
            if (kc + 1 < 16) {
                a00 = *(const uint4*)(arp0 + (kc + 1) * 32);
                a01 = *(const uint4*)(arp0 + (kc + 1) * 32 + 16);
                a10 = *(const uint4*)(arp1 + (kc + 1) * 32);
                a11 = *(const uint4*)(arp1 + (kc + 1) * 32 + 16);
            }
            const unsigned* As = smA + cur * STG_A;
#pragma unroll
            for (int ks = 0; ks < 4; ks++) {
                unsigned af[2][4], bfr[4][2];
#pragma unroll
                for (int mtw = 0; mtw < 2; mtw++) {
                    const unsigned* ap = &As[(wm + mtw * 16 + (lane >> 2)) * ASTR + ks * 8 + (lane & 3)];
                    af[mtw][0] = ap[0]; af[mtw][1] = ap[8 * ASTR]; af[mtw][2] = ap[4]; af[mtw][3] = ap[8 * ASTR + 4];
                }
#pragma unroll
                for (int ntw = 0; ntw < 4; ntw++) {
                    const unsigned* bp = &smV[(wn + ntw * 8 + (lane >> 2)) * VSTR + kc * 32 + ks * 8 + (lane & 3)];
                    bfr[ntw][0] = bp[0]; bfr[ntw][1] = bp[4];
                }
#pragma unroll
                for (int mtw = 0; mtw < 2; mtw++)
#pragma unroll
                    for (int ntw = 0; ntw < 4; ntw++)
                        mma_bf16(acc[mtw][ntw], af[mtw], bfr[ntw]);
            }
            if (kc + 1 < 16) {
                unsigned* Ad = smA + ((kc + 1) & 1) * STG_A;
                *(uint4*)&Ad[ldrow * ASTR + kcol]             = a00;
                *(uint4*)&Ad[ldrow * ASTR + kcol + 16]        = a01;
                *(uint4*)&Ad[(ldrow + 64) * ASTR + kcol]      = a10;
                *(uint4*)&Ad[(ldrow + 64) * ASTR + kcol + 16] = a11;
            }
            __syncthreads();
        }

        // accum -> smem gate tile (overlays A staging; all mma reads done)
#pragma unroll
        for (int mtw = 0; mtw < 2; mtw++)
#pragma unroll
            for (int ntw = 0; ntw < 4; ntw++) {
                int lr = wm + mtw * 16 + (lane >> 2);
                int lc = wn + ntw * 8 + (lane & 3) * 2;
                smG[lr * GS + lc]           = acc[mtw][ntw][0];
                smG[lr * GS + lc + 1]       = acc[mtw][ntw][1];
                smG[(lr + 8) * GS + lc]     = acc[mtw][ntw][2];
                smG[(lr + 8) * GS + lc + 1] = acc[mtw][ntw][3];
            }
        __syncthreads();

        // fused LSTM cell (c in registers)
        unsigned* hbout = g_hb[(t & 1) ^ 1];
#pragma unroll
        for (int it = 0; it < 4; it++) {
            int idx = tid + it * PTHREADS;
            int lr = idx >> 3, jp = idx & 7;
            int m = m0 + lr;
            float4 z0 = zpre[it][0];
            float4 z1 = zpre[it][1];
            const float* Gp = &smG[lr * GS + jp * 8];

            float i0 = fsig(Gp[0] + z0.x);
            float f0 = fsig(Gp[1] + z0.y);
            float g0 = tanhf(Gp[2] + z0.z);
            float o0 = fsig(Gp[3] + z0.w);
            float i1 = fsig(Gp[4] + z1.x);
            float f1 = fsig(Gp[5] + z1.y);
            float g1 = tanhf(Gp[6] + z1.z);
            float o1 = fsig(Gp[7] + z1.w);

            float cn0 = f0 * creg[it][0] + i0 * g0;
            float cn1 = f1 * creg[it][1] + i1 * g1;
            creg[it][0] = cn0; creg[it][1] = cn1;

            float h0v = o0 * tanhf(cn0);
            float h1v = o1 * tanhf(cn1);
            hbout[m * 512 + nsl * 8 + jp] = pack_bf2(h0v, h1v);
            if (t == SEQL - 1) {
                float2 hf; hf.x = h0v; hf.y = h1v;
                *(float2*)&g_h[0][m * HIDN + nsl * 16 + jp * 2] = hf;
            }
        }

        if (t < SEQL - 1) {
            __syncthreads();
            if (tid == 0) {
                __threadfence();
                atomicAdd(&g_bar, 1u);
                const unsigned target = (unsigned)NCTA * (t + 1);
                unsigned v;
                do {
                    asm volatile("ld.acquire.gpu.u32 %0, [%1];"
                                 : "=r"(v) : "l"(&g_bar) : "memory");
                } while (v < target);
            }
            __syncthreads();
        }
    }
}

// ---------------- tf32 output projection: out = h_final @ W^T + b ----------------
__global__ __launch_bounds__(128)
void out_gemm_kernel(const float* __restrict__ W,
                     const float* __restrict__ biasp,
                     float* __restrict__ Cout)
{
    const int tid  = threadIdx.x;
    const int lane = tid & 31;
    const int warp = tid >> 5;
    const int wm = (warp >> 1) * 64;
    const int wn = (warp & 1) * 32;
    const int n0 = blockIdx.x * BN;
    const int m0 = blockIdx.y * BM;

    __shared__ struct { float A[2][BM * AS]; float B[2][BN * BSS]; } sm;

    const float* Ain = g_h[0];
    const int kcol  = (tid & 3) * 4;
    const int ldrow = tid >> 2;

    const float* arp[4];
#pragma unroll
    for (int i = 0; i < 4; i++)
        arp[i] = Ain + (size_t)(m0 + ldrow + 32 * i) * HIDN + kcol;
    const float* brp[2];
#pragma unroll
    for (int i = 0; i < 2; i++)
        brp[i] = W + (size_t)(n0 + ldrow + 32 * i) * HIDN + kcol;

    float4 areg[4], breg[2];
    float acc[4][4][4];
#pragma unroll
    for (int a = 0; a < 4; a++)
#pragma unroll
        for (int b_ = 0; b_ < 4; b_++)
#pragma unroll
            for (int c_ = 0; c_ < 4; c_++) acc[a][b_][c_] = 0.f;

#pragma unroll
    for (int i = 0; i < 4; i++) areg[i] = *(const float4*)(arp[i]);
#pragma unroll
    for (int i = 0; i < 2; i++) breg[i] = *(const float4*)(brp[i]);
#pragma unroll
    for (int i = 0; i < 4; i++) {
        float4 v = areg[i];
        v.x = f2tf32(v.x); v.y = f2tf32(v.y); v.z = f2tf32(v.z); v.w = f2tf32(v.w);
        *(float4*)&sm.A[0][(ldrow + 32 * i) * AS + kcol] = v;
    }
#pragma unroll
    for (int i = 0; i < 2; i++) {
        float4 v = breg[i];
        v.x = f2tf32(v.x); v.y = f2tf32(v.y); v.z = f2tf32(v.z); v.w = f2tf32(v.w);
        *(float4*)&sm.B[0][(ldrow + 32 * i) * BSS + kcol] = v;
    }
    __syncthreads();

    const int NCH = HIDN / BK;
    for (int kc = 0; kc < NCH; kc++) {
        int cur = kc & 1;
        if (kc + 1 < NCH) {
#pragma unroll
            for (int i = 0; i < 4; i++) areg[i] = *(const float4*)(arp[i] + (kc + 1) * BK);
#pragma unroll
            for (int i = 0; i < 2; i++) breg[i] = *(const float4*)(brp[i] + (kc + 1) * BK);
        }
#pragma unroll
        for (int k8 = 0; k8 < BK; k8 += 8) {
            uint32_t af[4][4], bfr[4][2];
#pragma unroll
            for (int mt = 0; mt < 4; mt++) {
                const float* ap = &sm.A[cur][(wm + mt * 16 + (lane >> 2)) * AS + k8 + (lane & 3)];
                af[mt][0] = __float_as_uint(ap[0]);
                af[mt][1] = __float_as_uint(ap[8 * AS]);
                af[mt][2] = __float_as_uint(ap[4]);
                af[mt][3] = __float_as_uint(ap[8 * AS + 4]);
            }
#pragma unroll
            for (int nt = 0; nt < 4; nt++) {
                const float* bp = &sm.B[cur][(wn + nt * 8 + (lane >> 2)) * BSS + k8 + (lane & 3)];
                bfr[nt][0] = __float_as_uint(bp[0]);
                bfr[nt][1] = __float_as_uint(bp[4]);
            }
#pragma unroll
            for (int mt = 0; mt < 4; mt++)
#pragma unroll
                for (int nt = 0; nt < 4; nt++)
                    asm volatile(
                        "mma.sync.aligned.m16n8k8.row.col.f32.tf32.tf32.f32 "
                        "{%0,%1,%2,%3}, {%4,%5,%6,%7}, {%8,%9}, {%0,%1,%2,%3};"
                        : "+f"(acc[mt][nt][0]), "+f"(acc[mt][nt][1]),
                          "+f"(acc[mt][nt][2]), "+f"(acc[mt][nt][3])
                        : "r"(af[mt][0]), "r"(af[mt][1]), "r"(af[mt][2]), "r"(af[mt][3]),
                          "r"(bfr[nt][0]), "r"(bfr[nt][1]));
        }
        if (kc + 1 < NCH) {
            int nxt = cur ^ 1;
#pragma unroll
            for (int i = 0; i < 4; i++) {
                float4 v = areg[i];
                v.x = f2tf32(v.x); v.y = f2tf32(v.y); v.z = f2tf32(v.z); v.w = f2tf32(v.w);
                *(float4*)&sm.A[nxt][(ldrow + 32 * i) * AS + kcol] = v;
            }
#pragma unroll
            for (int i = 0; i < 2; i++) {
                float4 v = breg[i];
                v.x = f2tf32(v.x); v.y = f2tf32(v.y); v.z = f2tf32(v.z); v.w = f2tf32(v.w);
                *(float4*)&sm.B[nxt][(ldrow + 32 * i) * BSS + kcol] = v;
            }
        }
        __syncthreads();
    }

#pragma unroll
    for (int mt = 0; mt < 4; mt++) {
#pragma unroll
        for (int nt = 0; nt < 4; nt++) {
            int r = m0 + wm + mt * 16 + (lane >> 2);
            int cidx = n0 + wn + nt * 8 + (lane & 3) * 2;
            float2 bv = *(const float2*)&biasp[cidx];
            float2 v0; v0.x = acc[mt][nt][0] + bv.x; v0.y = acc[mt][nt][1] + bv.y;
            float2 v1; v1.x = acc[mt][nt][2] + bv.x; v1.y = acc[mt][nt][3] + bv.y;
            *(float2*)&Cout[(size_t)r * NCLS + cidx] = v0;
            *(float2*)&Cout[(size_t)(r + 8) * NCLS + cidx] = v1;
        }
    }
}

// ---------------- launch ----------------
extern "C" void kernel_launch(void* const* d_in, const int* in_sizes, int n_in,
                              void* d_out, int out_size)
{
    const int*   X   = (const int*)  d_in[0];
    const float* h0  = (const float*)d_in[1];
    const float* c0  = (const float*)d_in[2];
    const float* emb = (const float*)d_in[3];
    const float* Ui  = (const float*)d_in[4];
    const float* Vi  = (const float*)d_in[5];
    const float* bi  = (const float*)d_in[6];
    const float* Uf  = (const float*)d_in[7];
    const float* Vf  = (const float*)d_in[8];
    const float* bf  = (const float*)d_in[9];
    const float* Uc  = (const float*)d_in[10];
    const float* Vc  = (const float*)d_in[11];
    const float* bc  = (const float*)d_in[12];
    const float* Uo  = (const float*)d_in[13];
    const float* Vo  = (const float*)d_in[14];
    const float* bo  = (const float*)d_in[15];
    const float* W   = (const float*)d_in[16];
    const float* b   = (const float*)d_in[17];
    float* out = (float*)d_out;

    cudaFuncSetAttribute(lstm_persistent_kernel,
                         cudaFuncAttributeMaxDynamicSharedMemorySize, SMEM_P_BYTES);

    // 1) pack weights (bf16 interleaved), biases, init state, reset barrier
    pack_kernel<<<(NG * (HIDN / 2) + 255) / 256, 256>>>(Ui, Vi, bi, Uf, Vf, bf,
                                                        Uc, Vc, bc, Uo, Vo, bo, h0, c0);
    pack_emb_kernel<<<(int)(((size_t)NCLS * (EMBD / 2) + 255) / 256), 256>>>(emb);

    // 2) all input-side gate preactivations (bf16 tensor cores, 128x128 tiles)
    input_gemm_kernel<<<dim3(NG / 128, (SEQL * BATCH) / 128), 256>>>(X);

    // 3) all 128 recurrent steps in ONE persistent kernel (V resident in SMEM)
    lstm_persistent_kernel<<<NCTA, PTHREADS, SMEM_P_BYTES>>>();

    // 4) output projection (tf32): out = h_final @ W^T + b
    out_gemm_kernel<<<dim3(NCLS / BN, BATCH / BM), 128>>>(W, b, out);
}